// round 17
// baseline (speedup 1.0000x reference)
#include <cuda_runtime.h>
#include <math.h>

// ---------------------------------------------------------------------------
// SeFT network, round 16 (= R15 validated base, attnB fused into attnA):
//  - gather: fused ballot compaction, warp-shuffle prefix scan
//  - k_mlp: R8-validated dense128 (128 thr, 32-obs tiles, static smem) FROZEN
//  - attention: single kernel; per-chunk flash pass + last-block-done
//    atomic combine (deterministic: fixed summation order)
//  NOTE: tcgen05 unavailable (harness targets compute_103, ptxas rejects).
// ---------------------------------------------------------------------------

#define BMAX    32
#define LSTRIDE 2048
#define NCHUNK  16          // LSTRIDE / CLEN
#define CLEN    128
#define HID     128
#define NIN     34
#define ASTR    36

typedef unsigned long long ull;

__device__ float    g_St[BMAX * LSTRIDE];
__device__ float    g_Sc[BMAX * LSTRIDE];
__device__ float    g_Sx[BMAX * LSTRIDE];
__device__ int      g_lens[BMAX];
__device__ int      g_maxlen;
__device__ float    g_enc[(size_t)BMAX * LSTRIDE * HID];   // [b][l][e]
__device__ float    g_kT [(size_t)BMAX * HID * LSTRIDE];   // [b][e][l]
__device__ float    g_q  [BMAX * HID];
__device__ float    g_cm  [BMAX * 4 * NCHUNK];
__device__ float    g_csum[BMAX * 4 * NCHUNK];
__device__ float    g_part[(size_t)BMAX * NCHUNK * 512];
__device__ int      g_cnt[BMAX];     // zero-init; reset by combiner each replay

// ---- packed fp32x2 helpers -------------------------------------------------
__device__ __forceinline__ ull pack2(float x, float y) {
    ull r;
    asm("mov.b64 %0, {%1, %2};" : "=l"(r) : "f"(x), "f"(y));
    return r;
}
__device__ __forceinline__ void unpack2(ull v, float& lo, float& hi) {
    asm("mov.b64 {%0, %1}, %2;" : "=f"(lo), "=f"(hi) : "l"(v));
}
__device__ __forceinline__ ull ffma2(ull a, ull b, ull c) {
    ull d;
    asm("fma.rn.f32x2 %0, %1, %2, %3;" : "=l"(d) : "l"(a), "l"(b), "l"(c));
    return d;
}

// ---------------------------------------------------------------------------
// Kernel 1: fused gather. One block per patient (256 threads, 8 warps).
// ---------------------------------------------------------------------------
__global__ __launch_bounds__(256) void k_compact(
    const float* __restrict__ times,
    const int*   __restrict__ time_ptr,
    const float* __restrict__ X,
    const int*   __restrict__ M,
    int R, int V, int B, int n_times)
{
    int b = blockIdx.x;
    int t = threadIdx.x;
    int rpp = R / B;
    int r0 = b * rpp;
    int lane = t & 31, w = t >> 5;

    __shared__ int      scnt[256];
    __shared__ int      sstart[256];
    __shared__ int      swsum[8];
    __shared__ unsigned smask[256];
    __shared__ float    stime[256];

    scnt[t] = 0;

    for (int lr = w; lr < rpp; lr += 8) {
        int r = r0 + lr;
        int m = (lane < V) ? (M[r * V + lane] != 0) : 0;
        unsigned mask = __ballot_sync(0xffffffffu, m);
        if (lane == 0) {
            smask[lr] = mask;
            scnt[lr]  = __popc(mask);
            int lo = 0, hi = n_times - 1;
            while (lo < hi) {
                int mid = (lo + hi + 1) >> 1;
                if (time_ptr[mid] <= r) lo = mid; else hi = mid - 1;
            }
            stime[lr] = times[lo];
        }
    }
    __syncthreads();

    int cnt = scnt[t];
    int v = cnt;
#pragma unroll
    for (int o = 1; o < 32; o <<= 1) {
        int u = __shfl_up_sync(0xffffffffu, v, o);
        if (lane >= o) v += u;
    }
    if (lane == 31) swsum[w] = v;
    __syncthreads();
    int woff = 0;
#pragma unroll
    for (int q = 0; q < 8; q++) woff += (q < w) ? swsum[q] : 0;
    int tot = 0;
#pragma unroll
    for (int q = 0; q < 8; q++) tot += swsum[q];
    sstart[t] = woff + v - cnt;
    __syncthreads();

    for (int lr = w; lr < rpp; lr += 8) {
        int r = r0 + lr;
        unsigned mask = smask[lr];
        float tv = stime[lr];
        int start = sstart[lr];
        if (lane < V && ((mask >> lane) & 1u)) {
            int pos = start + __popc(mask & ((1u << lane) - 1u));
            if (pos < LSTRIDE) {
                g_St[b * LSTRIDE + pos] = tv;
                g_Sc[b * LSTRIDE + pos] = (float)lane;
                g_Sx[b * LSTRIDE + pos] = X[r * V + lane];
            }
        }
    }
    if (t == 0) {
        int L = min(tot, LSTRIDE);
        g_lens[b] = L;
        atomicMax(&g_maxlen, L);   // idempotent across replays
    }
}

// ---------------------------------------------------------------------------
// 128->128 dense layer, f32x2 (R8-validated, FROZEN).
// ---------------------------------------------------------------------------
__device__ __forceinline__ void dense128(const float* __restrict__ W,
                                         const float* __restrict__ bias,
                                         const float* sIn, float* wbuf,
                                         ull accA[8], ull accB[8],
                                         int r, int h, int tid)
{
    float bA = __ldg(&bias[r]);
    float bB = __ldg(&bias[r + 64]);
    ull iA = pack2(bA, bA), iB = pack2(bB, bB);
#pragma unroll
    for (int j = 0; j < 8; j++) { accA[j] = iA; accB[j] = iB; }

    for (int c = 0; c < 4; c++) {
        for (int i4 = tid; i4 < 1024; i4 += 128) {
            int e  = i4 << 2;
            int o  = e >> 5;
            int kk = e & 31;
            float4 v = __ldg((const float4*)(W + o * HID + c * 32 + kk));
            wbuf[kk * 129 + o]       = v.x;
            wbuf[(kk + 1) * 129 + o] = v.y;
            wbuf[(kk + 2) * 129 + o] = v.z;
            wbuf[(kk + 3) * 129 + o] = v.w;
        }
        __syncthreads();
#pragma unroll 4
        for (int kk = 0; kk < 32; kk++) {
            float wA = wbuf[kk * 129 + r];
            float wB = wbuf[kk * 129 + 64 + r];
            ull wA2 = pack2(wA, wA), wB2 = pack2(wB, wB);
            const ulonglong2* row =
                (const ulonglong2*)(sIn + (c * 32 + kk) * ASTR + h * 16);
#pragma unroll
            for (int p = 0; p < 4; p++) {
                ulonglong2 v = row[p];
                accA[2 * p]     = ffma2(v.x, wA2, accA[2 * p]);
                accA[2 * p + 1] = ffma2(v.y, wA2, accA[2 * p + 1]);
                accB[2 * p]     = ffma2(v.x, wB2, accB[2 * p]);
                accB[2 * p + 1] = ffma2(v.y, wB2, accB[2 * p + 1]);
            }
        }
        __syncthreads();
    }
}

__device__ __forceinline__ void epi_relu(float* dst, ull accA[8], ull accB[8],
                                         int r, int h)
{
    float* dA = dst + r * ASTR + h * 16;
    float* dB = dst + (r + 64) * ASTR + h * 16;
#pragma unroll
    for (int j = 0; j < 8; j++) {
        float lo, hi;
        unpack2(accA[j], lo, hi);
        *(ull*)(dA + 2 * j) = pack2(fmaxf(lo, 0.f), fmaxf(hi, 0.f));
        unpack2(accB[j], lo, hi);
        *(ull*)(dB + 2 * j) = pack2(fmaxf(lo, 0.f), fmaxf(hi, 0.f));
    }
}

// ---------------------------------------------------------------------------
// Kernel 2: fused MLP + projection, 32-obs tiles (R8-validated, FROZEN).
// ---------------------------------------------------------------------------
__global__ __launch_bounds__(128) void k_mlp(
    const float* __restrict__ W0, const float* __restrict__ b0,
    const float* __restrict__ W1, const float* __restrict__ b1,
    const float* __restrict__ W2, const float* __restrict__ b2,
    const float* __restrict__ Wk, const float* __restrict__ bk,
    const float* __restrict__ Wq, const float* __restrict__ bq,
    int B)
{
    __shared__ __align__(16) float sf[NIN * ASTR];
    __shared__ __align__(16) float sA[HID * ASTR];
    __shared__ __align__(16) float sB[HID * ASTR];

    int tid = threadIdx.x;
    int r = tid & 63;
    int h = tid >> 6;

    bool special = (blockIdx.x == 0);
    int b = 0, l0 = 0, nv = 0;
    if (!special) {
        int bi = blockIdx.x - 1;
        b = bi >> 6;
        int lt = bi & 63;
        int len = g_lens[b];
        l0 = lt * 32;
        if (l0 >= len) return;
        nv = min(32, len - l0);
    } else {
        nv = min(B, 32);
    }

    for (int i = tid; i < HID * NIN; i += 128) {
        int o = i / NIN, k = i - o * NIN;
        sA[k * 129 + o] = __ldg(&W0[i]);
    }

    if (tid < 32) {
        int o = tid;
        float tv = 0.f, cv = 0.f, xv = 0.f;
        if (special) {
            int L = g_maxlen;
            if (o < nv && L >= 1 && g_lens[o] == L) {
                tv = g_St[o * LSTRIDE + L - 1];
                cv = g_Sc[o * LSTRIDE + L - 1];
                xv = g_Sx[o * LSTRIDE + L - 1];
            }
        } else if (o < nv) {
            tv = g_St[b * LSTRIDE + l0 + o];
            cv = g_Sc[b * LSTRIDE + l0 + o];
            xv = g_Sx[b * LSTRIDE + l0 + o];
        }
#pragma unroll
        for (int i = 0; i < 16; i++) {
            float ts = powf(100.0f, (float)i * (1.0f / 15.0f));
            float sn, cs;
            sincosf(tv / ts, &sn, &cs);
            sf[i * ASTR + o]        = sn;
            sf[(16 + i) * ASTR + o] = cs;
        }
        sf[32 * ASTR + o] = cv;
        sf[33 * ASTR + o] = xv;
    }
    __syncthreads();

    ull accA[8], accB[8];

    // ---- layer 0 ----
    {
        float bA = __ldg(&b0[r]);
        float bB = __ldg(&b0[r + 64]);
        ull iA = pack2(bA, bA), iB = pack2(bB, bB);
#pragma unroll
        for (int j = 0; j < 8; j++) { accA[j] = iA; accB[j] = iB; }
#pragma unroll 2
        for (int k = 0; k < NIN; k++) {
            float wA = sA[k * 129 + r];
            float wB = sA[k * 129 + 64 + r];
            ull wA2 = pack2(wA, wA), wB2 = pack2(wB, wB);
            const ulonglong2* row = (const ulonglong2*)(sf + k * ASTR + h * 16);
#pragma unroll
            for (int p = 0; p < 4; p++) {
                ulonglong2 v = row[p];
                accA[2 * p]     = ffma2(v.x, wA2, accA[2 * p]);
                accA[2 * p + 1] = ffma2(v.y, wA2, accA[2 * p + 1]);
                accB[2 * p]     = ffma2(v.x, wB2, accB[2 * p]);
                accB[2 * p + 1] = ffma2(v.y, wB2, accB[2 * p + 1]);
            }
        }
        __syncthreads();
        epi_relu(sA, accA, accB, r, h);
    }
    __syncthreads();

    // ---- layer 1 ----
    dense128(W1, b1, sA, sB, accA, accB, r, h, tid);
    epi_relu(sB, accA, accB, r, h);
    __syncthreads();

    // ---- layer 2 (enc) ----
    dense128(W2, b2, sB, sA, accA, accB, r, h, tid);
    {
        float vA[16], vB[16];
#pragma unroll
        for (int j = 0; j < 8; j++) {
            unpack2(accA[j], vA[2 * j], vA[2 * j + 1]);
            unpack2(accB[j], vB[2 * j], vB[2 * j + 1]);
        }
        float* dA = sA + r * ASTR + h * 16;
        float* dB = sA + (r + 64) * ASTR + h * 16;
#pragma unroll
        for (int j = 0; j < 8; j++) {
            *(ull*)(dA + 2 * j) = accA[j];
            *(ull*)(dB + 2 * j) = accB[j];
        }
        if (!special) {
#pragma unroll
            for (int o = 0; o < 16; o++) {
                int og = h * 16 + o;
                if (og < nv) {
                    size_t base = ((size_t)b * LSTRIDE + l0 + og) * HID;
                    g_enc[base + r]      = vA[o];
                    g_enc[base + 64 + r] = vB[o];
                }
            }
        }
    }
    __syncthreads();

    // ---- projection ----
    dense128(special ? Wq : Wk, special ? bq : bk, sA, sB, accA, accB, r, h, tid);
    {
        float vA[16], vB[16];
#pragma unroll
        for (int j = 0; j < 8; j++) {
            unpack2(accA[j], vA[2 * j], vA[2 * j + 1]);
            unpack2(accB[j], vB[2 * j], vB[2 * j + 1]);
        }
        if (special) {
#pragma unroll
            for (int o = 0; o < 16; o++) {
                int og = h * 16 + o;
                if (og < nv) {
                    g_q[og * HID + r]      = vA[o];
                    g_q[og * HID + 64 + r] = vB[o];
                }
            }
        } else {
            float* gkA = g_kT + ((size_t)b * HID + r) * LSTRIDE + l0 + h * 16;
            float* gkB = g_kT + ((size_t)b * HID + 64 + r) * LSTRIDE + l0 + h * 16;
#pragma unroll
            for (int o = 0; o < 16; o += 4) {
                int og = h * 16 + o;
                if (og + 4 <= nv) {
                    *(float4*)(gkA + o) = make_float4(vA[o], vA[o+1], vA[o+2], vA[o+3]);
                    *(float4*)(gkB + o) = make_float4(vB[o], vB[o+1], vB[o+2], vB[o+3]);
                } else {
                    for (int m = 0; m < 4; m++)
                        if (og + m < nv) { gkA[o + m] = vA[o + m]; gkB[o + m] = vB[o + m]; }
                }
            }
        }
    }
}

// ---------------------------------------------------------------------------
// Kernel 3: attention, one kernel. grid (B, NCHUNK), 512 threads.
// Flash pass per chunk (validated R11 body) + last-block-done combine:
// the 16th block per patient performs the deterministic rescale-combine
// and writes out[b], then resets g_cnt[b] for the next graph replay.
// ---------------------------------------------------------------------------
__global__ __launch_bounds__(512) void k_attnA(float* __restrict__ out)
{
    int b = blockIdx.x, chunk = blockIdx.y, t = threadIdx.x;
    int len = min(g_lens[b], LSTRIDE);
    int l0 = chunk * CLEN;
    float* part = g_part + ((size_t)b * NCHUNK + chunk) * 512;

    extern __shared__ __align__(16) float dynA[];
    float* sq    = dynA;
    float* sbuf  = dynA + 128;
    float* sw4   = sbuf + 16512;
    float* sredw = sw4 + 512;
    float* smx   = sredw + 16;

    if (l0 >= len) {
        part[t] = 0.f;
        if (t < 4) {
            g_cm  [(b * 4 + t) * NCHUNK + chunk] = -1e30f;
            g_csum[(b * 4 + t) * NCHUNK + chunk] = 0.f;
        }
    } else {
        int nl = min(CLEN, len - l0);
        if (t < HID) sq[t] = g_q[b * HID + t];

        const float* kbase = g_kT + (size_t)b * HID * LSTRIDE + l0;
        for (int i = t; i < 4096; i += 512) {
            int e  = (i >> 3) & 127;
            int f4 = (i & 7) + ((i >> 10) << 3);
            float4 v = *(const float4*)(kbase + (size_t)e * LSTRIDE + f4 * 4);
            sbuf[(f4 * 4 + 0) * 129 + e] = v.x;
            sbuf[(f4 * 4 + 1) * 129 + e] = v.y;
            sbuf[(f4 * 4 + 2) * 129 + e] = v.z;
            sbuf[(f4 * 4 + 3) * 129 + e] = v.w;
        }
        __syncthreads();

        const float scale = 0.17677669529663687f;
        int l = t & 127, ha = t >> 7;
        int wid = t >> 5, lane = t & 31;

        float s = -1e30f;
        if (l < nl) {
            const float* kr = sbuf + l * 129 + ha * 32;
            const float* qr = sq + ha * 32;
            float a0 = 0.f, a1 = 0.f, a2 = 0.f, a3 = 0.f;
#pragma unroll
            for (int j = 0; j < 32; j += 4) {
                a0 = fmaf(kr[j],     qr[j],     a0);
                a1 = fmaf(kr[j + 1], qr[j + 1], a1);
                a2 = fmaf(kr[j + 2], qr[j + 2], a2);
                a3 = fmaf(kr[j + 3], qr[j + 3], a3);
            }
            s = ((a0 + a1) + (a2 + a3)) * scale;
        }

        {
            float v = s;
#pragma unroll
            for (int o = 16; o > 0; o >>= 1)
                v = fmaxf(v, __shfl_xor_sync(0xffffffffu, v, o));
            if (lane == 0) sredw[wid] = v;
        }
        __syncthreads();
        if (t < 4)
            smx[t] = fmaxf(fmaxf(sredw[t * 4], sredw[t * 4 + 1]),
                           fmaxf(sredw[t * 4 + 2], sredw[t * 4 + 3]));
        __syncthreads();

        float wv = (l < nl) ? expf(s - smx[ha]) : 0.f;
        sw4[l * 4 + ha] = wv;
        {
            float v = wv;
#pragma unroll
            for (int o = 16; o > 0; o >>= 1)
                v += __shfl_xor_sync(0xffffffffu, v, o);
            if (lane == 0) sredw[wid] = v;
        }
        __syncthreads();
        if (t < 4) {
            g_cm  [(b * 4 + t) * NCHUNK + chunk] = smx[t];
            g_csum[(b * 4 + t) * NCHUNK + chunk] =
                (sredw[t * 4] + sredw[t * 4 + 1]) + (sredw[t * 4 + 2] + sredw[t * 4 + 3]);
        }
        __syncthreads();

        const float* ebase = g_enc + ((size_t)b * LSTRIDE + l0) * HID;
        for (int i = t; i < 4096; i += 512)
            *(float4*)(sbuf + i * 4) = *(const float4*)(ebase + i * 4);
        __syncthreads();

        int ls = t >> 7, e = t & 127;
        float ac0 = 0.f, ac1 = 0.f, ac2 = 0.f, ac3 = 0.f;
        int lstart = ls * 32;
#pragma unroll 8
        for (int li = 0; li < 32; li++) {
            int ll = lstart + li;
            float ev = sbuf[ll * 128 + e];
            float4 w4 = *(const float4*)(sw4 + ll * 4);
            ac0 = fmaf(ev, w4.x, ac0);
            ac1 = fmaf(ev, w4.y, ac1);
            ac2 = fmaf(ev, w4.z, ac2);
            ac3 = fmaf(ev, w4.w, ac3);
        }
        __syncthreads();
        *(float4*)(sbuf + ((ls * 128 + e) << 2)) = make_float4(ac0, ac1, ac2, ac3);
        __syncthreads();

        {
            int ha2 = t >> 7, e2 = t & 127;
            float rr = 0.f;
#pragma unroll
            for (int q = 0; q < 4; q++)
                rr += sbuf[((q * 128 + e2) << 2) + ha2];
            part[t] = rr;
        }
    }

    // ---- last-block-done combine (deterministic) ----
    __threadfence();
    __shared__ int slast;
    if (t == 0) {
        int old = atomicAdd(&g_cnt[b], 1);
        slast = (old == NCHUNK - 1) ? 1 : 0;
    }
    __syncthreads();
    if (slast) {
        __threadfence();   // acquire: all 16 blocks' writes visible
        int h2 = t >> 7;
        int bh = b * 4 + h2;

        float m = -1e30f;
#pragma unroll
        for (int c = 0; c < NCHUNK; c++) m = fmaxf(m, g_cm[bh * NCHUNK + c]);

        float denom = 0.f, num = 0.f;
#pragma unroll
        for (int c = 0; c < NCHUNK; c++) {
            float f = expf(g_cm[bh * NCHUNK + c] - m);
            denom = fmaf(g_csum[bh * NCHUNK + c], f, denom);
            num   = fmaf(g_part[((size_t)b * NCHUNK + c) * 512 + t], f, num);
        }
        out[b * 512 + t] = num / denom;

        if (t == 0) g_cnt[b] = 0;   // reset for next graph replay
    }
}

// ---------------------------------------------------------------------------
extern "C" void kernel_launch(void* const* d_in, const int* in_sizes, int n_in,
                              void* d_out, int out_size)
{
    const float* times    = (const float*)d_in[0];
    const int*   time_ptr = (const int*)  d_in[1];
    const float* X        = (const float*)d_in[2];
    const int*   M        = (const int*)  d_in[3];
    const float* W0 = (const float*)d_in[6];
    const float* b0 = (const float*)d_in[7];
    const float* W1 = (const float*)d_in[8];
    const float* b1 = (const float*)d_in[9];
    const float* W2 = (const float*)d_in[10];
    const float* b2 = (const float*)d_in[11];
    const float* Wq = (const float*)d_in[12];
    const float* bq = (const float*)d_in[13];
    const float* Wk = (const float*)d_in[14];
    const float* bk = (const float*)d_in[15];

    int R       = in_sizes[0];
    int n_times = in_sizes[0];
    int V       = in_sizes[2] / R;
    int B       = in_sizes[5];

    const int ATTN_SMEM = (128 + 128 * 129 + 512 + 16 + 4) * (int)sizeof(float);
    cudaFuncSetAttribute(k_attnA, cudaFuncAttributeMaxDynamicSharedMemorySize,
                         ATTN_SMEM);

    k_compact<<<B, 256>>>(times, time_ptr, X, M, R, V, B, n_times);
    k_mlp<<<B * 64 + 1, 128>>>(W0, b0, W1, b1, W2, b2, Wk, bk, Wq, bq, B);
    dim3 gs(B, NCHUNK);
    k_attnA<<<gs, 512, ATTN_SMEM>>>((float*)d_out);
}